// round 1
// baseline (speedup 1.0000x reference)
#include <cuda_runtime.h>
#include <cstdint>

// ---------------- problem constants ----------------
#define BATCH  4
#define SEQ    2048
#define DMODEL 1024
#define DINNER 2048
#define DSTATE 16
#define DCONV  4
#define NROWS  (BATCH * SEQ)            // 8192 token rows
#define XPW    (2 * DSTATE + DINNER)    // 2080 (dt_raw | B_ssm | C)

// ---------------- scratch (static device globals; no allocation) ----------------
__device__ float g_xz[(size_t)NROWS * (2 * DINNER)];  // in_proj output [8192, 4096]
__device__ float g_xs[(size_t)NROWS * DINNER];        // conv+silu x-stream [8192, 2048]
__device__ float g_xp[(size_t)NROWS * XPW];           // x_proj output [8192, 2080]
__device__ float g_dt[(size_t)NROWS * DINNER];        // softplus(dt) [8192, 2048]
__device__ float g_y [(size_t)NROWS * DINNER];        // pre-out_proj activations

// ---------------- GEMM: C[M,N] = A[M,K] @ B[N,K]^T (all row-major) ----------------
// 128x128 block tile, BK=16, 8x8 thread tile, 256 threads.
// Inner product uses packed fma.rn.f32x2 (2 FMA lanes per instr on sm_103a).
#define BM 128
#define BN 128
#define BK 16
#define TM 8
#define TN 8

__global__ __launch_bounds__(256, 2)
void gemm_tn(const float* __restrict__ A, const float* __restrict__ B,
             float* __restrict__ C, int M, int N, int K) {
    __shared__ float As[BK][BM];
    __shared__ float Bs[BK][BN];

    const int tid  = threadIdx.x;
    const int row0 = blockIdx.y * BM;
    const int col0 = blockIdx.x * BN;
    const int tx   = tid & 15;   // 0..15 -> N direction
    const int ty   = tid >> 4;   // 0..15 -> M direction

    unsigned long long acc[TM][TN / 2];
    #pragma unroll
    for (int m = 0; m < TM; m++)
        #pragma unroll
        for (int j = 0; j < TN / 2; j++) acc[m][j] = 0ull;

    for (int k0 = 0; k0 < K; k0 += BK) {
        // Stage A tile (transposed into k-major smem)
        #pragma unroll
        for (int i = 0; i < 2; i++) {
            int idx = tid + i * 256;          // 0..511
            int r   = idx >> 2;               // tile row 0..127
            int kk4 = (idx & 3) << 2;         // k offset 0,4,8,12
            float4 v = *(const float4*)(A + (size_t)(row0 + r) * K + k0 + kk4);
            As[kk4 + 0][r] = v.x; As[kk4 + 1][r] = v.y;
            As[kk4 + 2][r] = v.z; As[kk4 + 3][r] = v.w;
        }
        // Stage B tile (guard ragged N, e.g. N=2080)
        #pragma unroll
        for (int i = 0; i < 2; i++) {
            int idx = tid + i * 256;
            int r   = idx >> 2;
            int kk4 = (idx & 3) << 2;
            float4 v = make_float4(0.f, 0.f, 0.f, 0.f);
            if (col0 + r < N)
                v = *(const float4*)(B + (size_t)(col0 + r) * K + k0 + kk4);
            Bs[kk4 + 0][r] = v.x; Bs[kk4 + 1][r] = v.y;
            Bs[kk4 + 2][r] = v.z; Bs[kk4 + 3][r] = v.w;
        }
        __syncthreads();

        #pragma unroll
        for (int kk = 0; kk < BK; kk++) {
            float4 a0 = *(const float4*)&As[kk][ty * TM];
            float4 a1 = *(const float4*)&As[kk][ty * TM + 4];
            ulonglong2 bq0 = *(const ulonglong2*)&Bs[kk][tx * TN];
            ulonglong2 bq1 = *(const ulonglong2*)&Bs[kk][tx * TN + 4];
            unsigned long long bb[4] = {bq0.x, bq0.y, bq1.x, bq1.y};
            float av[8] = {a0.x, a0.y, a0.z, a0.w, a1.x, a1.y, a1.z, a1.w};
            #pragma unroll
            for (int m = 0; m < TM; m++) {
                unsigned long long aa;
                asm("mov.b64 %0, {%1, %1};" : "=l"(aa) : "f"(av[m]));
                #pragma unroll
                for (int j = 0; j < 4; j++)
                    asm("fma.rn.f32x2 %0, %1, %2, %0;"
                        : "+l"(acc[m][j]) : "l"(aa), "l"(bb[j]));
            }
        }
        __syncthreads();
    }

    // Epilogue
    #pragma unroll
    for (int m = 0; m < TM; m++) {
        int row = row0 + ty * TM + m;
        #pragma unroll
        for (int j = 0; j < TN / 2; j++) {
            int col = col0 + tx * TN + 2 * j;
            float lo = __uint_as_float((unsigned)(acc[m][j] & 0xffffffffull));
            float hi = __uint_as_float((unsigned)(acc[m][j] >> 32));
            if (col < N)     C[(size_t)row * N + col]     = lo;
            if (col + 1 < N) C[(size_t)row * N + col + 1] = hi;
        }
    }
}

// ---------------- depthwise causal conv(4) + bias + silu ----------------
__global__ void conv_silu_kernel(const float* __restrict__ conv_w,
                                 const float* __restrict__ conv_b) {
    int idx = blockIdx.x * blockDim.x + threadIdx.x;
    if (idx >= NROWS * DINNER) return;
    int d   = idx & (DINNER - 1);
    int row = idx >> 11;            // / 2048
    int l   = row & (SEQ - 1);
    float acc = conv_b[d];
    #pragma unroll
    for (int j = 0; j < DCONV; j++) {
        int ls = l - (DCONV - 1) + j;
        if (ls >= 0)
            acc = fmaf(conv_w[d * DCONV + j],
                       g_xz[(size_t)(row - (DCONV - 1) + j) * (2 * DINNER) + d], acc);
    }
    g_xs[idx] = acc / (1.f + expf(-acc));   // silu
}

// ---------------- dt = softplus(dt_raw @ W_dt^T + b_dt) ----------------
__global__ void dt_kernel(const float* __restrict__ W_dt,
                          const float* __restrict__ b_dt) {
    int idx = blockIdx.x * blockDim.x + threadIdx.x;
    if (idx >= NROWS * DINNER) return;
    int d   = idx & (DINNER - 1);
    int row = idx >> 11;
    const float4* xr4 = (const float4*)(g_xp + (size_t)row * XPW);   // first 16 floats
    const float4* w4  = (const float4*)(W_dt + d * DSTATE);
    float s = b_dt[d];
    #pragma unroll
    for (int q = 0; q < 4; q++) {
        float4 w = w4[q], xv = xr4[q];
        s = fmaf(w.x, xv.x, fmaf(w.y, xv.y, fmaf(w.z, xv.z, fmaf(w.w, xv.w, s))));
    }
    g_dt[idx] = (s > 20.f) ? s : log1pf(expf(s));
}

// ---------------- selective scan + skip + gate ----------------
// One thread per (b, d). Loads along d are warp-coalesced at each timestep.
__global__ void scan_kernel(const float* __restrict__ A_log,
                            const float* __restrict__ Dvec) {
    int d = blockIdx.x * blockDim.x + threadIdx.x;  // 0..2047
    int b = blockIdx.y;

    float Am[DSTATE];
    #pragma unroll
    for (int n = 0; n < DSTATE; n++) Am[n] = -expf(A_log[d * DSTATE + n]);  // A row
    float h[DSTATE];
    #pragma unroll
    for (int n = 0; n < DSTATE; n++) h[n] = 0.f;
    float Dd = Dvec[d];

    for (int t = 0; t < SEQ; t++) {
        size_t row = (size_t)b * SEQ + t;
        float xv  = g_xs[row * DINNER + d];
        float dtv = g_dt[row * DINNER + d];
        const float* xpr = g_xp + row * XPW;
        float Cv  = xpr[2 * DSTATE + d];
        float zv  = g_xz[row * (2 * DINNER) + DINNER + d];
        float4 B0 = *(const float4*)(xpr + DSTATE + 0);
        float4 B1 = *(const float4*)(xpr + DSTATE + 4);
        float4 B2 = *(const float4*)(xpr + DSTATE + 8);
        float4 B3 = *(const float4*)(xpr + DSTATE + 12);
        float Bv[DSTATE] = {B0.x, B0.y, B0.z, B0.w, B1.x, B1.y, B1.z, B1.w,
                            B2.x, B2.y, B2.z, B2.w, B3.x, B3.y, B3.z, B3.w};
        float u = dtv * xv;
        float s = 0.f;
        #pragma unroll
        for (int n = 0; n < DSTATE; n++) {
            float g = __expf(dtv * Am[n]);
            h[n] = fmaf(h[n], g, u * Bv[n]);
            s += h[n];
        }
        float yv  = fmaf(xv, Dd, s * Cv);
        float sig = 1.f / (1.f + __expf(-zv));
        g_y[row * DINNER + d] = yv * (zv * sig);
    }
}

// ---------------- launch ----------------
extern "C" void kernel_launch(void* const* d_in, const int* in_sizes, int n_in,
                              void* d_out, int out_size) {
    const float* x      = (const float*)d_in[0];
    const float* W_in   = (const float*)d_in[1];
    const float* conv_w = (const float*)d_in[2];
    const float* conv_b = (const float*)d_in[3];
    const float* W_x    = (const float*)d_in[4];
    const float* W_dt   = (const float*)d_in[5];
    const float* b_dt   = (const float*)d_in[6];
    const float* A_log  = (const float*)d_in[7];
    const float* Dv     = (const float*)d_in[8];
    const float* W_out  = (const float*)d_in[9];
    float* out = (float*)d_out;

    float *p_xz, *p_xs, *p_xp, *p_y;
    cudaGetSymbolAddress((void**)&p_xz, g_xz);
    cudaGetSymbolAddress((void**)&p_xs, g_xs);
    cudaGetSymbolAddress((void**)&p_xp, g_xp);
    cudaGetSymbolAddress((void**)&p_y,  g_y);

    // 1) xz = x @ W_in^T                  [8192, 4096]
    gemm_tn<<<dim3((2 * DINNER) / BN, NROWS / BM), 256>>>(x, W_in, p_xz,
                                                          NROWS, 2 * DINNER, DMODEL);
    // 2) xs = silu(causal_conv(xz[:, :2048]) + b)
    conv_silu_kernel<<<(NROWS * DINNER) / 256, 256>>>(conv_w, conv_b);
    // 3) xp = xs @ W_x^T                  [8192, 2080]
    gemm_tn<<<dim3((XPW + BN - 1) / BN, NROWS / BM), 256>>>(p_xs, W_x, p_xp,
                                                            NROWS, XPW, DINNER);
    // 4) dt = softplus(xp[:, :16] @ W_dt^T + b_dt)
    dt_kernel<<<(NROWS * DINNER) / 256, 256>>>(W_dt, b_dt);
    // 5) selective scan + skip + gate -> g_y
    scan_kernel<<<dim3(DINNER / 64, BATCH), 64>>>(A_log, Dv);
    // 6) out = y @ W_out^T                [8192, 1024]
    gemm_tn<<<dim3(DMODEL / BN, NROWS / BM), 256>>>(p_y, W_out, out,
                                                    NROWS, DMODEL, DINNER);
}

// round 4
// speedup vs baseline: 2.0914x; 2.0914x over previous
#include <cuda_runtime.h>
#include <cuda_bf16.h>
#include <cstdint>

// ---------------- problem constants ----------------
#define BATCH  4
#define SEQ    2048
#define DMODEL 1024
#define DINNER 2048
#define DSTATE 16
#define DCONV  4
#define NROWS  (BATCH * SEQ)            // 8192 token rows
#define XPW    (2 * DSTATE + DINNER)    // 2080 (dt_raw | B_ssm | C)
#define WXPAD  2176                     // W_x rows padded to mult of 128

// ---------------- scratch (static device globals; no allocation) ----------------
__device__ float g_xz[(size_t)NROWS * (2 * DINNER)];   // in_proj output [8192, 4096]
__device__ float g_xs[(size_t)NROWS * DINNER];         // conv+silu fp32 (scan input)
__device__ float g_xp[(size_t)NROWS * XPW];            // x_proj output [8192, 2080]
__device__ float g_dt[(size_t)NROWS * DINNER];         // softplus(dt)

__device__ __nv_bfloat16 g_x_hi [(size_t)NROWS * DMODEL];
__device__ __nv_bfloat16 g_x_lo [(size_t)NROWS * DMODEL];
__device__ __nv_bfloat16 g_xs_hi[(size_t)NROWS * DINNER];
__device__ __nv_bfloat16 g_xs_lo[(size_t)NROWS * DINNER];
__device__ __nv_bfloat16 g_y_hi [(size_t)NROWS * DINNER];
__device__ __nv_bfloat16 g_y_lo [(size_t)NROWS * DINNER];
__device__ __nv_bfloat16 g_Win_hi [(size_t)(2 * DINNER) * DMODEL];
__device__ __nv_bfloat16 g_Win_lo [(size_t)(2 * DINNER) * DMODEL];
__device__ __nv_bfloat16 g_Wx_hi  [(size_t)WXPAD * DINNER];
__device__ __nv_bfloat16 g_Wx_lo  [(size_t)WXPAD * DINNER];
__device__ __nv_bfloat16 g_Wout_hi[(size_t)DMODEL * DINNER];
__device__ __nv_bfloat16 g_Wout_lo[(size_t)DMODEL * DINNER];

// ---------------- PTX helpers (base-arch features only) ----------------
__device__ __forceinline__ uint32_t smem_u32(const void* p) {
    uint32_t a;
    asm("{ .reg .u64 t; cvta.to.shared.u64 t, %1; cvt.u32.u64 %0, t; }" : "=r"(a) : "l"(p));
    return a;
}
__device__ __forceinline__ void cpa16(uint32_t dst, const void* src) {
    asm volatile("cp.async.cg.shared.global [%0], [%1], 16;" :: "r"(dst), "l"(src));
}
#define CPA_COMMIT() asm volatile("cp.async.commit_group;" ::: "memory")
#define CPA_WAIT(n)  asm volatile("cp.async.wait_group %0;" :: "n"(n) : "memory")

__device__ __forceinline__ void ldsm4(uint32_t* r, uint32_t addr) {
    asm volatile("ldmatrix.sync.aligned.m8n8.x4.shared.b16 {%0,%1,%2,%3}, [%4];"
                 : "=r"(r[0]), "=r"(r[1]), "=r"(r[2]), "=r"(r[3]) : "r"(addr));
}
__device__ __forceinline__ void mma16816(float* c, const uint32_t* a, const uint32_t* b) {
    asm volatile("mma.sync.aligned.m16n8k16.row.col.f32.bf16.bf16.f32 "
                 "{%0,%1,%2,%3}, {%4,%5,%6,%7}, {%8,%9}, {%0,%1,%2,%3};"
                 : "+f"(c[0]), "+f"(c[1]), "+f"(c[2]), "+f"(c[3])
                 : "r"(a[0]), "r"(a[1]), "r"(a[2]), "r"(a[3]), "r"(b[0]), "r"(b[1]));
}

// ---------------- mma.sync split-bf16 GEMM ----------------
// C[M,N] = A[M,K] @ B[N,K]^T; A,B given as bf16 (hi,lo) pairs, K-major.
// CTA tile 128x128, 8 warps (2x4), warp tile 64x32, BK=32, cp.async 2-stage.
// Smem rows padded to 40 bf16 (80B stride): row offsets mod 128B all distinct
// 16B slots -> ldmatrix conflict-free.
#define RSTR   40                        // padded row stride (elements)
#define TSZ    (128 * RSTR * 2)          // one tensor tile: 10240 B
#define GSTAGE (4 * TSZ)                 // Ahi|Alo|Bhi|Blo: 40960 B
#define GEMM_SMEM (2 * GSTAGE)           // 81920 B

__global__ __launch_bounds__(256, 1)
void gemm_tc(const __nv_bfloat16* __restrict__ Ahi, const __nv_bfloat16* __restrict__ Alo,
             const __nv_bfloat16* __restrict__ Bhi, const __nv_bfloat16* __restrict__ Blo,
             float* __restrict__ C, int Nst, int K, int ldC) {
    extern __shared__ char smem[];
    const uint32_t sbase = smem_u32(smem);
    const int tid  = threadIdx.x;
    const int wid  = tid >> 5, lane = tid & 31;
    const int wm   = wid & 1;            // warp m index (0..1) -> m offset wm*64
    const int wn   = wid >> 1;           // warp n index (0..3) -> n offset wn*32
    const int row0 = blockIdx.y * 128;
    const int col0 = blockIdx.x * 128;

    const __nv_bfloat16* baseP[4] = {
        Ahi + (size_t)row0 * K, Alo + (size_t)row0 * K,
        Bhi + (size_t)col0 * K, Blo + (size_t)col0 * K };

    // per-thread ldmatrix address components
    const int a_row = wm * 64 + (lane & 7) + ((lane >> 3) & 1) * 8;  // + mt*16
    const int a_cb  = ((lane >> 4) & 1) * 16;                        // byte offset in k
    const int b_row = wn * 32 + ((lane >> 4) << 3) + (lane & 7);     // + ntp*16
    const int b_cb  = ((lane >> 3) & 1) * 16;

    // cp.async indices: idx in [0,512) per tensor; r=idx/4, c=idx%4
    const int nch = K >> 5;              // K / 32

    float acc[4][4][4];
    #pragma unroll
    for (int mt = 0; mt < 4; mt++)
        #pragma unroll
        for (int nt = 0; nt < 4; nt++)
            #pragma unroll
            for (int q = 0; q < 4; q++) acc[mt][nt][q] = 0.f;

    // prologue: chunk 0 -> stage 0
    {
        const uint32_t st = sbase;
        #pragma unroll
        for (int t = 0; t < 4; t++) {
            const __nv_bfloat16* P = baseP[t];
            #pragma unroll
            for (int i = 0; i < 2; i++) {
                int idx = i * 256 + tid;
                int r = idx >> 2, c = idx & 3;
                cpa16(st + t * TSZ + r * (RSTR * 2) + c * 16, P + (size_t)r * K + c * 8);
            }
        }
        CPA_COMMIT();
    }

    for (int ci = 0; ci < nch; ci++) {
        const uint32_t stc = sbase + (uint32_t)(ci & 1) * GSTAGE;
        // prefetch next chunk into other stage
        if (ci + 1 < nch) {
            const uint32_t stn = sbase + (uint32_t)((ci + 1) & 1) * GSTAGE;
            const int koff = (ci + 1) << 5;
            #pragma unroll
            for (int t = 0; t < 4; t++) {
                const __nv_bfloat16* P = baseP[t] + koff;
                #pragma unroll
                for (int i = 0; i < 2; i++) {
                    int idx = i * 256 + tid;
                    int r = idx >> 2, c = idx & 3;
                    cpa16(stn + t * TSZ + r * (RSTR * 2) + c * 16, P + (size_t)r * K + c * 8);
                }
            }
            CPA_COMMIT();
            CPA_WAIT(1);
        } else {
            CPA_WAIT(0);
        }
        __syncthreads();

        const uint32_t pAh = stc;
        const uint32_t pAl = stc + TSZ;
        const uint32_t pBh = stc + 2 * TSZ;
        const uint32_t pBl = stc + 3 * TSZ;

        #pragma unroll
        for (int ks = 0; ks < 2; ks++) {
            const int kb = ks * 32;      // byte offset of k16 step within row (16 bf16)
            uint32_t ah[4][4], al[4][4], bh[4][2], bl[4][2];
            #pragma unroll
            for (int mt = 0; mt < 4; mt++) {
                uint32_t off = (uint32_t)(a_row + mt * 16) * (RSTR * 2) + kb + a_cb;
                ldsm4(ah[mt], pAh + off);
                ldsm4(al[mt], pAl + off);
            }
            #pragma unroll
            for (int ntp = 0; ntp < 2; ntp++) {
                uint32_t off = (uint32_t)(b_row + ntp * 16) * (RSTR * 2) + kb + b_cb;
                uint32_t r4[4];
                ldsm4(r4, pBh + off);
                bh[2 * ntp][0] = r4[0]; bh[2 * ntp][1] = r4[1];
                bh[2 * ntp + 1][0] = r4[2]; bh[2 * ntp + 1][1] = r4[3];
                ldsm4(r4, pBl + off);
                bl[2 * ntp][0] = r4[0]; bl[2 * ntp][1] = r4[1];
                bl[2 * ntp + 1][0] = r4[2]; bl[2 * ntp + 1][1] = r4[3];
            }
            #pragma unroll
            for (int mt = 0; mt < 4; mt++)
                #pragma unroll
                for (int nt = 0; nt < 4; nt++) {
                    mma16816(acc[mt][nt], ah[mt], bh[nt]);
                    mma16816(acc[mt][nt], ah[mt], bl[nt]);
                    mma16816(acc[mt][nt], al[mt], bh[nt]);
                }
        }
        __syncthreads();
    }

    // epilogue: direct stores (thread holds col pairs)
    #pragma unroll
    for (int mt = 0; mt < 4; mt++) {
        const int r0 = row0 + wm * 64 + mt * 16 + (lane >> 2);
        #pragma unroll
        for (int nt = 0; nt < 4; nt++) {
            const int cc = col0 + wn * 32 + nt * 8 + (lane & 3) * 2;
            if (cc + 1 < Nst) {
                *(float2*)(C + (size_t)r0 * ldC + cc) =
                    make_float2(acc[mt][nt][0], acc[mt][nt][1]);
                *(float2*)(C + (size_t)(r0 + 8) * ldC + cc) =
                    make_float2(acc[mt][nt][2], acc[mt][nt][3]);
            } else if (cc < Nst) {
                C[(size_t)r0 * ldC + cc]       = acc[mt][nt][0];
                C[(size_t)(r0 + 8) * ldC + cc] = acc[mt][nt][2];
            }
        }
    }
}

// ---------------- fp32 -> bf16 (hi, lo) conversion with row padding ----------------
__global__ void cvt_pair_kernel(const float* __restrict__ src,
                                __nv_bfloat16* __restrict__ hi, __nv_bfloat16* __restrict__ lo,
                                int rows_src, int K, int rows_pad) {
    size_t i = (size_t)blockIdx.x * blockDim.x + threadIdx.x;
    if (i >= (size_t)rows_pad * K) return;
    int r = (int)(i / K);
    float v = (r < rows_src) ? src[i] : 0.f;
    __nv_bfloat16 h = __float2bfloat16_rn(v);
    hi[i] = h;
    lo[i] = __float2bfloat16_rn(v - __bfloat162float(h));
}

// ---------------- depthwise causal conv(4) + bias + silu (+ bf16 pair out) ----------------
__global__ void conv_silu_kernel(const float* __restrict__ conv_w,
                                 const float* __restrict__ conv_b) {
    int idx = blockIdx.x * blockDim.x + threadIdx.x;
    if (idx >= NROWS * DINNER) return;
    int d   = idx & (DINNER - 1);
    int row = idx >> 11;
    int l   = row & (SEQ - 1);
    float acc = conv_b[d];
    #pragma unroll
    for (int j = 0; j < DCONV; j++) {
        int ls = l - (DCONV - 1) + j;
        if (ls >= 0)
            acc = fmaf(conv_w[d * DCONV + j],
                       g_xz[(size_t)(row - (DCONV - 1) + j) * (2 * DINNER) + d], acc);
    }
    float v = acc / (1.f + __expf(-acc));   // silu
    g_xs[idx] = v;
    __nv_bfloat16 h = __float2bfloat16_rn(v);
    g_xs_hi[idx] = h;
    g_xs_lo[idx] = __float2bfloat16_rn(v - __bfloat162float(h));
}

// ---------------- dt = softplus(dt_raw @ W_dt^T + b_dt), smem-tiled ----------------
__global__ __launch_bounds__(256)
void dt_kernel(const float* __restrict__ W_dt, const float* __restrict__ b_dt) {
    __shared__ float sxp[32][DSTATE];
    const int d  = blockIdx.x * 256 + threadIdx.x;
    const int r0 = blockIdx.y * 32;
    for (int i = threadIdx.x; i < 32 * DSTATE; i += 256) {
        int rr = i >> 4, cc = i & 15;
        sxp[rr][cc] = g_xp[(size_t)(r0 + rr) * XPW + cc];
    }
    __syncthreads();
    float4 w0 = *(const float4*)(W_dt + d * DSTATE + 0);
    float4 w1 = *(const float4*)(W_dt + d * DSTATE + 4);
    float4 w2 = *(const float4*)(W_dt + d * DSTATE + 8);
    float4 w3 = *(const float4*)(W_dt + d * DSTATE + 12);
    const float bb = b_dt[d];
    #pragma unroll 4
    for (int i = 0; i < 32; i++) {
        const float* xr = sxp[i];
        float s = bb;
        s = fmaf(w0.x, xr[0],  fmaf(w0.y, xr[1],  fmaf(w0.z, xr[2],  fmaf(w0.w, xr[3],  s))));
        s = fmaf(w1.x, xr[4],  fmaf(w1.y, xr[5],  fmaf(w1.z, xr[6],  fmaf(w1.w, xr[7],  s))));
        s = fmaf(w2.x, xr[8],  fmaf(w2.y, xr[9],  fmaf(w2.z, xr[10], fmaf(w2.w, xr[11], s))));
        s = fmaf(w3.x, xr[12], fmaf(w3.y, xr[13], fmaf(w3.z, xr[14], fmaf(w3.w, xr[15], s))));
        g_dt[(size_t)(r0 + i) * DINNER + d] = (s > 20.f) ? s : log1pf(__expf(s));
    }
}

// ---------------- selective scan + skip + gate (bf16 pair out) ----------------
// One thread per (b, d). exp(dt*A[n]) computed as r^(n+1) (A rows are -(1..16))
// with a per-thread structure check falling back to generic exp.
__global__ void scan_kernel(const float* __restrict__ A_log,
                            const float* __restrict__ Dvec) {
    const int d = blockIdx.x * 64 + threadIdx.x;
    const int b = blockIdx.y;

    float Am[DSTATE];
    #pragma unroll
    for (int n = 0; n < DSTATE; n++) Am[n] = -expf(A_log[d * DSTATE + n]);
    bool pw = true;
    #pragma unroll
    for (int n = 1; n < DSTATE; n++)
        pw = pw && (fabsf(Am[n] - (float)(n + 1) * Am[0]) <= 1e-4f * fabsf(Am[n]));

    float h[DSTATE];
    #pragma unroll
    for (int n = 0; n < DSTATE; n++) h[n] = 0.f;
    const float Dd = Dvec[d];

    for (int t = 0; t < SEQ; t++) {
        const size_t row = (size_t)b * SEQ + t;
        const float xv  = g_xs[row * DINNER + d];
        const float dtv = g_dt[row * DINNER + d];
        const float* xpr = g_xp + row * XPW;
        const float Cv  = xpr[2 * DSTATE + d];
        const float zv  = g_xz[row * (2 * DINNER) + DINNER + d];
        float4 B0 = *(const float4*)(xpr + DSTATE + 0);
        float4 B1 = *(const float4*)(xpr + DSTATE + 4);
        float4 B2 = *(const float4*)(xpr + DSTATE + 8);
        float4 B3 = *(const float4*)(xpr + DSTATE + 12);
        const float Bv[DSTATE] = {B0.x, B0.y, B0.z, B0.w, B1.x, B1.y, B1.z, B1.w,
                                  B2.x, B2.y, B2.z, B2.w, B3.x, B3.y, B3.z, B3.w};
        float g[DSTATE];
        if (pw) {
            const float r  = __expf(dtv * Am[0]);
            const float r2 = r * r;
            g[0] = r; g[1] = r2;
            #pragma unroll
            for (int n = 2; n < DSTATE; n++) g[n] = g[n - 2] * r2;   // two chains, depth 8
        } else {
            #pragma unroll
            for (int n = 0; n < DSTATE; n++) g[n] = __expf(dtv * Am[n]);
        }
        const float u = dtv * xv;
        #pragma unroll
        for (int n = 0; n < DSTATE; n++) h[n] = fmaf(h[n], g[n], u * Bv[n]);
        float s0 = (h[0] + h[1]) + (h[2] + h[3]);
        float s1 = (h[4] + h[5]) + (h[6] + h[7]);
        float s2 = (h[8] + h[9]) + (h[10] + h[11]);
        float s3 = (h[12] + h[13]) + (h[14] + h[15]);
        const float s = (s0 + s1) + (s2 + s3);
        const float yv  = fmaf(xv, Dd, s * Cv);
        const float sig = 1.f / (1.f + __expf(-zv));
        const float yg  = yv * (zv * sig);
        __nv_bfloat16 hi = __float2bfloat16_rn(yg);
        g_y_hi[row * DINNER + d] = hi;
        g_y_lo[row * DINNER + d] = __float2bfloat16_rn(yg - __bfloat162float(hi));
    }
}

// ---------------- launch ----------------
extern "C" void kernel_launch(void* const* d_in, const int* in_sizes, int n_in,
                              void* d_out, int out_size) {
    const float* x      = (const float*)d_in[0];
    const float* W_in   = (const float*)d_in[1];
    const float* conv_w = (const float*)d_in[2];
    const float* conv_b = (const float*)d_in[3];
    const float* W_x    = (const float*)d_in[4];
    const float* W_dt   = (const float*)d_in[5];
    const float* b_dt   = (const float*)d_in[6];
    const float* A_log  = (const float*)d_in[7];
    const float* Dv     = (const float*)d_in[8];
    const float* W_out  = (const float*)d_in[9];
    float* out = (float*)d_out;

    cudaFuncSetAttribute(gemm_tc, cudaFuncAttributeMaxDynamicSharedMemorySize, GEMM_SMEM);

    float *p_xz, *p_xp;
    cudaGetSymbolAddress((void**)&p_xz, g_xz);
    cudaGetSymbolAddress((void**)&p_xp, g_xp);
    __nv_bfloat16 *xh, *xl, *wih, *wil, *xsh, *xsl, *wxh, *wxl, *yh, *yl, *woh, *wol;
    cudaGetSymbolAddress((void**)&xh,  g_x_hi);   cudaGetSymbolAddress((void**)&xl,  g_x_lo);
    cudaGetSymbolAddress((void**)&wih, g_Win_hi); cudaGetSymbolAddress((void**)&wil, g_Win_lo);
    cudaGetSymbolAddress((void**)&xsh, g_xs_hi);  cudaGetSymbolAddress((void**)&xsl, g_xs_lo);
    cudaGetSymbolAddress((void**)&wxh, g_Wx_hi);  cudaGetSymbolAddress((void**)&wxl, g_Wx_lo);
    cudaGetSymbolAddress((void**)&yh,  g_y_hi);   cudaGetSymbolAddress((void**)&yl,  g_y_lo);
    cudaGetSymbolAddress((void**)&woh, g_Wout_hi);cudaGetSymbolAddress((void**)&wol, g_Wout_lo);

    // 0) fp32 -> bf16 hi/lo conversions (weights + x)
    cvt_pair_kernel<<<(2 * DINNER * DMODEL) / 256, 256>>>(W_in, wih, wil, 2 * DINNER, DMODEL, 2 * DINNER);
    cvt_pair_kernel<<<(WXPAD * DINNER) / 256, 256>>>(W_x, wxh, wxl, XPW, DINNER, WXPAD);
    cvt_pair_kernel<<<(DMODEL * DINNER) / 256, 256>>>(W_out, woh, wol, DMODEL, DINNER, DMODEL);
    cvt_pair_kernel<<<(NROWS * DMODEL) / 256, 256>>>(x, xh, xl, NROWS, DMODEL, NROWS);

    // 1) xz = x @ W_in^T   [8192, 4096]
    gemm_tc<<<dim3(2 * DINNER / 128, NROWS / 128), 256, GEMM_SMEM>>>(
        xh, xl, wih, wil, p_xz, 2 * DINNER, DMODEL, 2 * DINNER);

    // 2) xs = silu(causal_conv(xz[:, :2048]) + b)  (+ bf16 pair)
    conv_silu_kernel<<<(NROWS * DINNER) / 256, 256>>>(conv_w, conv_b);

    // 3) xp = xs @ W_x^T   [8192, 2080] (B padded to 2176 rows)
    gemm_tc<<<dim3(WXPAD / 128, NROWS / 128), 256, GEMM_SMEM>>>(
        xsh, xsl, wxh, wxl, p_xp, XPW, DINNER, XPW);

    // 4) dt = softplus(xp[:, :16] @ W_dt^T + b_dt)
    dt_kernel<<<dim3(DINNER / 256, NROWS / 32), 256>>>(W_dt, b_dt);

    // 5) selective scan + skip + gate -> y (bf16 pair)
    scan_kernel<<<dim3(DINNER / 64, BATCH), 64>>>(A_log, Dv);

    // 6) out = y @ W_out^T  [8192, 1024]
    gemm_tc<<<dim3(DMODEL / 128, NROWS / 128), 256, GEMM_SMEM>>>(
        yh, yl, woh, wol, out, DMODEL, DINNER, DMODEL);
}